// round 1
// baseline (speedup 1.0000x reference)
#include <cuda_runtime.h>
#include <cstdint>

// Problem constants (validated against in_sizes at launch)
#define NN 50000
#define EE 625000
#define D0 128
#define D1 128
#define D2 64

// Scratch (device globals — no allocation allowed)
__device__ float g_deg [NN];
__device__ float g_dinv[NN];
__device__ float g_h1  [(size_t)NN * D1];
__device__ float g_agg1[(size_t)NN * D1];
__device__ float g_h2  [(size_t)NN * D2];

// ---------------------------------------------------------------------------
// Degree / normalization
// ---------------------------------------------------------------------------
__global__ void k_init_deg(int n) {
    int i = blockIdx.x * blockDim.x + threadIdx.x;
    if (i < n) g_deg[i] = 1.0f;            // self-loop
}

__global__ void k_count_deg(const int* __restrict__ ei, int E) {
    int e = blockIdx.x * blockDim.x + threadIdx.x;
    if (e < E) atomicAdd(&g_deg[ei[E + e]], 1.0f);
}

__global__ void k_dinv(int n) {
    int i = blockIdx.x * blockDim.x + threadIdx.x;
    if (i < n) g_dinv[i] = rsqrtf(g_deg[i]);   // deg >= 1 always (self-loop)
}

// ---------------------------------------------------------------------------
// Register-blocked fp32 GEMM: OUT[row][c] = sum_k A'[row][k] * W[c][k]
//   A' = relu(A + bin) if IN_ACT else A
//   H   <- acc                      (pre-norm result, needed by scatter)
//   AGG <- dinv[row]^2 * acc (+bout)  (self-loop contribution, bias folded)
// Block: 256 threads, 64 rows x NOUT cols. W tile + X tile fully in smem,
// both stored k-major; thread (tx,ty) computes 4 rows x (NOUT/64 groups of 4
// cols at stride 64) -> conflict-free LDS.128 on both operands.
// ---------------------------------------------------------------------------
template <int NOUT, bool IN_ACT, bool OUT_BIAS>
__global__ __launch_bounds__(256, 2)
void k_gemm(const float* __restrict__ A, const float* __restrict__ W,
            const float* __restrict__ bin, const float* __restrict__ bout,
            float* __restrict__ H, float* __restrict__ AGG, int M)
{
    constexpr int K  = 128;
    constexpr int TM = 64;
    constexpr int WS = NOUT + 4;   // smem row stride for W (k-major)
    constexpr int XS = TM + 4;     // smem row stride for X (k-major)
    constexpr int NG = NOUT / 64;  // column groups per thread (2 or 1)

    extern __shared__ float sm[];
    float* Ws = sm;                // [K][WS]
    float* Xs = sm + K * WS;       // [K][XS]

    const int tid  = threadIdx.x;
    const int row0 = blockIdx.x * TM;

    // ---- load W transposed into smem: Ws[k][c] = W[c*K + k]
    for (int fid = tid; fid < NOUT * (K / 4); fid += 256) {
        int c  = fid >> 5;          // K/4 = 32 float4 per W row
        int kq = fid & 31;
        float4 w = *reinterpret_cast<const float4*>(W + (size_t)c * K + kq * 4);
        Ws[(kq * 4 + 0) * WS + c] = w.x;
        Ws[(kq * 4 + 1) * WS + c] = w.y;
        Ws[(kq * 4 + 2) * WS + c] = w.z;
        Ws[(kq * 4 + 3) * WS + c] = w.w;
    }

    // ---- load X tile transposed (+ optional relu(x+b1)): Xs[k][r]
    for (int fid = tid; fid < TM * (K / 4); fid += 256) {
        int r   = fid >> 5;
        int kq  = fid & 31;
        int row = row0 + r;
        float4 v = make_float4(0.f, 0.f, 0.f, 0.f);
        if (row < M)
            v = *reinterpret_cast<const float4*>(A + (size_t)row * K + kq * 4);
        if (IN_ACT) {
            v.x = fmaxf(v.x + __ldg(bin + kq * 4 + 0), 0.f);
            v.y = fmaxf(v.y + __ldg(bin + kq * 4 + 1), 0.f);
            v.z = fmaxf(v.z + __ldg(bin + kq * 4 + 2), 0.f);
            v.w = fmaxf(v.w + __ldg(bin + kq * 4 + 3), 0.f);
        }
        Xs[(kq * 4 + 0) * XS + r] = v.x;
        Xs[(kq * 4 + 1) * XS + r] = v.y;
        Xs[(kq * 4 + 2) * XS + r] = v.z;
        Xs[(kq * 4 + 3) * XS + r] = v.w;
    }
    __syncthreads();

    const int tx = tid & 15;        // 16 col-threads
    const int ty = tid >> 4;        // 16 row-threads
    const int r0 = ty * 4;

    float acc[4][NG][4];
    #pragma unroll
    for (int i = 0; i < 4; i++)
        #pragma unroll
        for (int g = 0; g < NG; g++)
            #pragma unroll
            for (int j = 0; j < 4; j++) acc[i][g][j] = 0.f;

    #pragma unroll 8
    for (int k = 0; k < K; k++) {
        float4 xv = *reinterpret_cast<const float4*>(&Xs[k * XS + r0]);
        float xr[4] = {xv.x, xv.y, xv.z, xv.w};
        float4 wv[NG];
        #pragma unroll
        for (int g = 0; g < NG; g++)
            wv[g] = *reinterpret_cast<const float4*>(&Ws[k * WS + tx * 4 + g * 64]);
        #pragma unroll
        for (int i = 0; i < 4; i++)
            #pragma unroll
            for (int g = 0; g < NG; g++) {
                acc[i][g][0] = fmaf(xr[i], wv[g].x, acc[i][g][0]);
                acc[i][g][1] = fmaf(xr[i], wv[g].y, acc[i][g][1]);
                acc[i][g][2] = fmaf(xr[i], wv[g].z, acc[i][g][2]);
                acc[i][g][3] = fmaf(xr[i], wv[g].w, acc[i][g][3]);
            }
    }

    // ---- epilogue: H = acc ; AGG = dinv^2 * acc (+ bout)
    #pragma unroll
    for (int i = 0; i < 4; i++) {
        int row = row0 + r0 + i;
        if (row < M) {
            float s = g_dinv[row];
            s = s * s;
            #pragma unroll
            for (int g = 0; g < NG; g++) {
                int c = tx * 4 + g * 64;
                float4 hv = make_float4(acc[i][g][0], acc[i][g][1],
                                        acc[i][g][2], acc[i][g][3]);
                *reinterpret_cast<float4*>(H + (size_t)row * NOUT + c) = hv;
                float4 av;
                if (OUT_BIAS) {
                    av.x = fmaf(s, hv.x, __ldg(bout + c + 0));
                    av.y = fmaf(s, hv.y, __ldg(bout + c + 1));
                    av.z = fmaf(s, hv.z, __ldg(bout + c + 2));
                    av.w = fmaf(s, hv.w, __ldg(bout + c + 3));
                } else {
                    av = make_float4(s * hv.x, s * hv.y, s * hv.z, s * hv.w);
                }
                *reinterpret_cast<float4*>(AGG + (size_t)row * NOUT + c) = av;
            }
        }
    }
}

// ---------------------------------------------------------------------------
// Edge scatter: AGG[dst] += dinv[src]*dinv[dst] * H[src], via red.global.v4
// Layer 1: 128 floats/edge -> one warp per edge (lane -> float4)
// ---------------------------------------------------------------------------
__device__ __forceinline__ void red_add_v4(float* p, float a, float b, float c, float d) {
    asm volatile("red.global.add.v4.f32 [%0], {%1, %2, %3, %4};"
                 :: "l"(p), "f"(a), "f"(b), "f"(c), "f"(d) : "memory");
}

__global__ void k_scatter128(const float* __restrict__ H, const int* __restrict__ ei,
                             float* __restrict__ AGG, int E)
{
    int e    = (blockIdx.x * blockDim.x + threadIdx.x) >> 5;
    int lane = threadIdx.x & 31;
    if (e >= E) return;
    int s = __ldg(ei + e);
    int d = __ldg(ei + E + e);
    float c = g_dinv[s] * g_dinv[d];
    float4 v = *(reinterpret_cast<const float4*>(H + (size_t)s * 128) + lane);
    red_add_v4(AGG + (size_t)d * 128 + lane * 4, c * v.x, c * v.y, c * v.z, c * v.w);
}

// Layer 2: 64 floats/edge -> half-warp per edge
__global__ void k_scatter64(const float* __restrict__ H, const int* __restrict__ ei,
                            float* __restrict__ AGG, int E)
{
    int idx = blockIdx.x * blockDim.x + threadIdx.x;
    int e   = idx >> 4;
    int l   = idx & 15;
    if (e >= E) return;
    int s = __ldg(ei + e);
    int d = __ldg(ei + E + e);
    float c = g_dinv[s] * g_dinv[d];
    float4 v = *(reinterpret_cast<const float4*>(H + (size_t)s * 64) + l);
    red_add_v4(AGG + (size_t)d * 64 + l * 4, c * v.x, c * v.y, c * v.z, c * v.w);
}

// ---------------------------------------------------------------------------
extern "C" void kernel_launch(void* const* d_in, const int* in_sizes, int n_in,
                              void* d_out, int out_size)
{
    const float* x  = (const float*)d_in[0];
    const int*   ei = (const int*)  d_in[1];
    const float* W1 = (const float*)d_in[2];
    const float* b1 = (const float*)d_in[3];
    const float* W2 = (const float*)d_in[4];
    const float* b2 = (const float*)d_in[5];
    float* out = (float*)d_out;

    const int N = in_sizes[0] / D0;   // 50000
    const int E = in_sizes[1] / 2;    // 625000

    // Device-global scratch addresses
    float *p_h1, *p_agg1, *p_h2;
    cudaGetSymbolAddress((void**)&p_h1,   g_h1);
    cudaGetSymbolAddress((void**)&p_agg1, g_agg1);
    cudaGetSymbolAddress((void**)&p_h2,   g_h2);

    const int SMEM1 = (128 * (D1 + 4) + 128 * (64 + 4)) * 4;  // 102400 B
    const int SMEM2 = (128 * (D2 + 4) + 128 * (64 + 4)) * 4;  //  69632 B
    cudaFuncSetAttribute(k_gemm<D1, false, false>,
                         cudaFuncAttributeMaxDynamicSharedMemorySize, SMEM1);
    cudaFuncSetAttribute(k_gemm<D2, true, true>,
                         cudaFuncAttributeMaxDynamicSharedMemorySize, SMEM2);

    // 1. degree (with self-loop) and dinv
    k_init_deg <<<(N + 255) / 256, 256>>>(N);
    k_count_deg<<<(E + 255) / 256, 256>>>(ei, E);
    k_dinv     <<<(N + 255) / 256, 256>>>(N);

    // 2. layer 1: h1 = x@W1^T ; agg1 = dinv^2*h1 ; then edge scatter
    k_gemm<D1, false, false><<<(N + 63) / 64, 256, SMEM1>>>(
        x, W1, nullptr, nullptr, p_h1, p_agg1, N);
    k_scatter128<<<(E + 7) / 8, 256>>>(p_h1, ei, p_agg1, E);

    // 3. layer 2: h2 = relu(agg1+b1)@W2^T ; out = dinv^2*h2 + b2 ; scatter
    k_gemm<D2, true, true><<<(N + 63) / 64, 256, SMEM2>>>(
        p_agg1, W2, b1, b2, p_h2, out, N);
    k_scatter64<<<(E + 15) / 16, 256>>>(p_h2, ei, out, E);
}